// round 17
// baseline (speedup 1.0000x reference)
#include <cuda_runtime.h>
#include <cuda_fp16.h>
#include <stdint.h>

// Problem constants (fixed for GCN_69097433858735)
#define NN 100000
#define EE 3200000
#define FIN 128
#define HH 16
#define CC 2
#define T 256
#define NB 592          // 148 SMs x 4 blocks — guaranteed co-resident (<=152x4 on GB300)

// Static scratch (zero-initialized at load; g_cnt zero-invariant restored in phase 6)
__device__ int   g_cnt [NN];                      // in-degree (edges only)
__device__ float g_dinv[NN];                      // rsqrt(deg+1)
__device__ __align__(16) float  g_h   [NN * HH];  // x@W1 (unscaled)
__device__ __align__(16) __half g_hsh [NN * HH];  // h * dinv[n]  (fp16 scatter payload)
__device__ __align__(16) float  g_acc1[NN * HH];  // seeded with self-loop di*h
__device__ __align__(16) float  g_gs  [NN * CC];  // (relu_out @ W2) * dinv[n]
__device__ __align__(16) float  g_acc2[NN * CC];  // seeded with self-loop gs

// software grid barrier state (generation-based; replay-safe)
__device__ int          g_bar_cnt;
__device__ volatile int g_bar_gen;

__device__ __forceinline__ unsigned h2_bits(__half2 h) {
    return *reinterpret_cast<unsigned*>(&h);
}

// Grid barrier: all NB blocks are co-resident by construction, so spinning is safe.
__device__ __forceinline__ void gbar() {
    __syncthreads();
    if (threadIdx.x == 0) {
        __threadfence();                       // publish this block's writes
        int gen = g_bar_gen;
        if (atomicAdd(&g_bar_cnt, 1) == NB - 1) {
            g_bar_cnt = 0;
            __threadfence();
            g_bar_gen = gen + 1;               // release
        } else {
            while (g_bar_gen == gen) __nanosleep(64);
        }
        __threadfence();                       // acquire
    }
    __syncthreads();
}

__global__ __launch_bounds__(T, 4)
void k_persist(const float* __restrict__ x,
               const int*   __restrict__ ei,
               const float* __restrict__ W1,
               const float* __restrict__ b1,
               const float* __restrict__ W2,
               const float* __restrict__ b2,
               float* __restrict__ out,
               int n, int e) {
    __shared__ float sW1[FIN * HH];   // 8 KB (reused as dead space after phase 1)
    __shared__ float sW2[HH * CC];
    __shared__ float sb1[HH];

    const int tid  = threadIdx.x;
    const int gid  = blockIdx.x * T + tid;
    const int nbt  = NB * T;
    const int lane = tid & 31;
    const int wgid = blockIdx.x * (T / 32) + (tid >> 5);   // global warp id
    const int nwarp = NB * (T / 32);

    // ---- phase 1a: gemm  h = x@W1 (2 threads/row, grid-stride) ----
    for (int i = tid; i < FIN * HH; i += T) sW1[i] = W1[i];
    __syncthreads();

    for (int t = gid; t < 2 * n; t += nbt) {
        int row  = t >> 1;
        int half = t & 1;
        float acc[HH];
#pragma unroll
        for (int j = 0; j < HH; j++) acc[j] = 0.0f;
        const float4* xr = (const float4*)(x + (long long)row * FIN) + half * 16;
        const float*  w  = sW1 + half * 64 * HH;
#pragma unroll 8
        for (int k4 = 0; k4 < 16; k4++) {
            float4 xv = __ldg(&xr[k4]);
            int k = k4 * 4;
#pragma unroll
            for (int j = 0; j < HH; j++) {
                acc[j] += xv.x * w[(k + 0) * HH + j];
                acc[j] += xv.y * w[(k + 1) * HH + j];
                acc[j] += xv.z * w[(k + 2) * HH + j];
                acc[j] += xv.w * w[(k + 3) * HH + j];
            }
        }
#pragma unroll
        for (int j = 0; j < HH; j++)
            acc[j] += __shfl_xor_sync(0xffffffffu, acc[j], 1);
        float4* h4 = (float4*)(g_h + (long long)row * HH);
#pragma unroll
        for (int q = 0; q < 2; q++) {
            int qq = half * 2 + q;
            h4[qq] = make_float4(acc[qq * 4 + 0], acc[qq * 4 + 1],
                                 acc[qq * 4 + 2], acc[qq * 4 + 3]);
        }
    }

    // ---- phase 1b: degree count (int4, 4 edges/thread, grid-stride) ----
    {
        const int* dstp = ei + e;
        for (int i4 = gid; i4 * 4 < e; i4 += nbt) {
            int base = i4 * 4;
            if (base + 3 < e) {
                int4 d4 = *(const int4*)(dstp + base);
                int a = d4.x, b = d4.y, c = d4.z, d = d4.w;
                if ((unsigned)a >= NN) a = 0;
                if ((unsigned)b >= NN) b = 0;
                if ((unsigned)c >= NN) c = 0;
                if ((unsigned)d >= NN) d = 0;
                atomicAdd(&g_cnt[a], 1);
                atomicAdd(&g_cnt[b], 1);
                atomicAdd(&g_cnt[c], 1);
                atomicAdd(&g_cnt[d], 1);
            } else {
                for (int i = base; i < e; i++) {
                    int d = dstp[i];
                    if ((unsigned)d >= NN) d = 0;
                    atomicAdd(&g_cnt[d], 1);
                }
            }
        }
    }
    gbar();

    // ---- phase 2: scale  dinv, hsh = fp16(h*di), acc1 = di*h (self-loop seed) ----
    for (int t = gid; t < 2 * n; t += nbt) {
        int row = t >> 1;
        int hf  = t & 1;
        float di = rsqrtf((float)(g_cnt[row] + 1));
        if (hf == 0) g_dinv[row] = di;
        const float4* h4 = (const float4*)(g_h + (long long)row * HH) + hf * 2;
        float4 a = h4[0];
        float4 b = h4[1];
        a.x *= di; a.y *= di; a.z *= di; a.w *= di;
        b.x *= di; b.y *= di; b.z *= di; b.w *= di;
        uint4 packed;
        packed.x = h2_bits(__floats2half2_rn(a.x, a.y));
        packed.y = h2_bits(__floats2half2_rn(a.z, a.w));
        packed.z = h2_bits(__floats2half2_rn(b.x, b.y));
        packed.w = h2_bits(__floats2half2_rn(b.z, b.w));
        *((uint4*)(g_hsh + (long long)row * HH) + hf) = packed;
        float4* a4 = (float4*)(g_acc1 + (long long)row * HH) + hf * 2;
        a4[0] = a;
        a4[1] = b;
    }
    gbar();

    // ---- phase 3: scatter1  acc1[dst] += hs[src]  (4 lanes/edge, 32 edges/warp) ----
    {
        int k = lane >> 2;
        int q = lane & 3;
        float4* accbase = (float4*)g_acc1;
        for (long long wb = (long long)wgid * 32; wb < e; wb += (long long)nwarp * 32) {
            long long idx = wb + lane;
            int tS = 0, tD = 0;
            if (idx < e) {
                tS = ei[idx];
                tD = ei[e + idx];
            }
#pragma unroll
            for (int j = 0; j < 4; j++) {
                int slot = k + j * 8;
                if (wb + slot >= e) break;
                int s = __shfl_sync(0xffffffffu, tS, slot);
                int d = __shfl_sync(0xffffffffu, tD, slot);
                if ((unsigned)s >= NN) s = 0;
                if ((unsigned)d >= NN) d = 0;
                uint2 raw = __ldg((const uint2*)(g_hsh + (long long)s * HH) + q);
                float2 f0 = __half22float2(*(__half2*)&raw.x);
                float2 f1 = __half22float2(*(__half2*)&raw.y);
                atomicAdd(accbase + (long long)d * 4 + q,
                          make_float4(f0.x, f0.y, f1.x, f1.y));
            }
        }
    }
    gbar();

    // ---- phase 4: fin1+gemm2  gs = (relu(di*acc1 + b1) @ W2) * di; acc2 seed ----
    for (int i = tid; i < HH * CC; i += T) sW2[i] = b1 ? W2[i] : 0.f;
    for (int i = tid; i < HH; i += T) sb1[i] = b1[i];
    __syncthreads();

    for (int row = gid; row < n; row += nbt) {
        float di = g_dinv[row];
        const float4* ac4 = (const float4*)(g_acc1 + (long long)row * HH);
        float gc0 = 0.f, gc1 = 0.f;
#pragma unroll
        for (int q = 0; q < HH / 4; q++) {
            float4 a = ac4[q];
            float o0 = fmaxf(di * a.x + sb1[q * 4 + 0], 0.f);
            float o1 = fmaxf(di * a.y + sb1[q * 4 + 1], 0.f);
            float o2 = fmaxf(di * a.z + sb1[q * 4 + 2], 0.f);
            float o3 = fmaxf(di * a.w + sb1[q * 4 + 3], 0.f);
            gc0 += o0 * sW2[(q * 4 + 0) * CC + 0] + o1 * sW2[(q * 4 + 1) * CC + 0]
                 + o2 * sW2[(q * 4 + 2) * CC + 0] + o3 * sW2[(q * 4 + 3) * CC + 0];
            gc1 += o0 * sW2[(q * 4 + 0) * CC + 1] + o1 * sW2[(q * 4 + 1) * CC + 1]
                 + o2 * sW2[(q * 4 + 2) * CC + 1] + o3 * sW2[(q * 4 + 3) * CC + 1];
        }
        float2 g = make_float2(gc0 * di, gc1 * di);
        *(float2*)(g_gs   + (long long)row * CC) = g;
        *(float2*)(g_acc2 + (long long)row * CC) = g;
    }
    gbar();

    // ---- phase 5: scatter2  acc2[dst] += gs[src]  (4 edges/thread, int4) ----
    for (int i4 = gid; i4 * 4 < e; i4 += nbt) {
        int i = i4 * 4;
        if (i + 3 < e) {
            int4 s4 = *(const int4*)(ei + i);
            int4 d4 = *(const int4*)(ei + e + i);
            int s0 = s4.x, s1 = s4.y, s2 = s4.z, s3 = s4.w;
            int d0 = d4.x, d1 = d4.y, d2 = d4.z, d3 = d4.w;
            if ((unsigned)s0 >= NN) s0 = 0;
            if ((unsigned)s1 >= NN) s1 = 0;
            if ((unsigned)s2 >= NN) s2 = 0;
            if ((unsigned)s3 >= NN) s3 = 0;
            if ((unsigned)d0 >= NN) d0 = 0;
            if ((unsigned)d1 >= NN) d1 = 0;
            if ((unsigned)d2 >= NN) d2 = 0;
            if ((unsigned)d3 >= NN) d3 = 0;
            float2 v0 = __ldg((const float2*)(g_gs + (long long)s0 * CC));
            float2 v1 = __ldg((const float2*)(g_gs + (long long)s1 * CC));
            float2 v2 = __ldg((const float2*)(g_gs + (long long)s2 * CC));
            float2 v3 = __ldg((const float2*)(g_gs + (long long)s3 * CC));
            atomicAdd((float2*)(g_acc2 + (long long)d0 * CC), v0);
            atomicAdd((float2*)(g_acc2 + (long long)d1 * CC), v1);
            atomicAdd((float2*)(g_acc2 + (long long)d2 * CC), v2);
            atomicAdd((float2*)(g_acc2 + (long long)d3 * CC), v3);
        } else {
            for (; i < e; i++) {
                int s = ei[i];
                int d = ei[e + i];
                if ((unsigned)s >= NN) s = 0;
                if ((unsigned)d >= NN) d = 0;
                float2 v = __ldg((const float2*)(g_gs + (long long)s * CC));
                atomicAdd((float2*)(g_acc2 + (long long)d * CC), v);
            }
        }
    }
    gbar();

    // ---- phase 6: final  out = di*acc2 + b2; restore g_cnt zeros ----
    float bb0 = b2[0], bb1 = b2[1];
    for (int row = gid; row < n; row += nbt) {
        float di = g_dinv[row];
        float2 a = *((const float2*)(g_acc2 + (long long)row * CC));
        float2 o;
        o.x = di * a.x + bb0;
        o.y = di * a.y + bb1;
        *((float2*)(out + (long long)row * CC)) = o;
        g_cnt[row] = 0;
    }
}

extern "C" void kernel_launch(void* const* d_in, const int* in_sizes, int n_in,
                              void* d_out, int out_size) {
    const float* x  = (const float*)d_in[0];
    const int*   ei = (const int*)d_in[1];    // int32 (JAX x64 disabled)
    const float* W1 = (const float*)d_in[2];
    const float* b1 = (const float*)d_in[3];
    const float* W2 = (const float*)d_in[4];
    const float* b2 = (const float*)d_in[5];
    float* out = (float*)d_out;

    int n = in_sizes[0] / FIN;     // 100000
    int e = in_sizes[1] / 2;       // 3200000

    k_persist<<<NB, T>>>(x, ei, W1, b1, W2, b2, out, n, e);
}